// round 17
// baseline (speedup 1.0000x reference)
#include <cuda_runtime.h>
#include <cuda_bf16.h>
#include <math.h>
#include <stdint.h>

#define TT 8
#define NNODE 40000
#define FF 256
#define PP 128
#define GG 128
#define HH 128
#define BB 1024
#define NE 640000
#define NNZ (NE + NNODE)
#define MALL (TT * NNODE)      // 320000 batched rows

// ------------------------- device scratch -------------------------
__device__ __align__(16) float g_h  [(size_t)MALL * PP];
__device__ __align__(16) float g_m  [(size_t)MALL * GG];
__device__ __align__(16) float g_hc [(size_t)MALL * GG];
__device__ __align__(16) float g_mc [(size_t)TT * BB * GG];
__device__ __align__(16) float g_h2 [(size_t)TT * BB * GG];
__device__ __align__(16) float g_tgt[(size_t)TT * BB * (2 * GG)];
__device__ __align__(16) float g_gi [(size_t)TT * BB * (3 * HH)];
__device__ __align__(16) float g_wihT[(size_t)(2 * GG) * (3 * HH)];
__device__ __align__(16) float g_outs[(size_t)TT * BB * HH];
__device__ __align__(16) float g_val [NNZ];
__device__ __align__(16) float g_dinv[NNODE];
__device__ __align__(16) int   g_col [NNZ];
__device__ __align__(16) int   g_rowptr[NNODE + 1];
__device__ __align__(16) int   g_deg [NNODE];
__device__ __align__(16) int   g_fill[NNODE];
__device__ __align__(16) int   g_src [NE];
__device__ __align__(16) int   g_dst [NE];
__device__ __align__(16) int   g_ti  [BB];
__device__ __align__(16) int   g_tmask[NNODE];
__device__ __align__(16) int   g_smask[NNODE];
__device__ __align__(16) int   g_snodes[NNODE];
__device__ __align__(16) int   g_sidx [NNODE];
__device__ __align__(16) int   g_tidx [NNODE];
__device__ __align__(16) int   g_tnodes[BB];
__device__ int g_nt;
__device__ int g_ns;
__device__ int g_is64;

// ------------------------- packed f32x2 FMA -------------------------
__device__ __forceinline__ void ffma2(unsigned long long& d, unsigned long long a,
                                      unsigned long long b) {
    asm("fma.rn.f32x2 %0, %1, %2, %0;" : "+l"(d) : "l"(a), "l"(b));
}
__device__ __forceinline__ unsigned long long bcast2(float v) {
    unsigned long long o;
    uint32_t u = __float_as_uint(v);
    asm("mov.b64 %0, {%1, %1};" : "=l"(o) : "r"(u));
    return o;
}
__device__ __forceinline__ void unpk2(float& lo, float& hi, unsigned long long p) {
    uint32_t a, b;
    asm("mov.b64 {%0, %1}, %2;" : "=r"(a), "=r"(b) : "l"(p));
    lo = __uint_as_float(a);
    hi = __uint_as_float(b);
}

// ------------------------- SGEMM (128x128x16, 8x8/thread, FFMA2) — R15 winner --------
template<int AS, int BS, int CS, int MSEL, bool RELU, bool BIAS>
__global__ void __launch_bounds__(256) sgemm2(const float* __restrict__ Aext,
                                              const float* __restrict__ Bext,
                                              const float* __restrict__ bias,
                                              int Mparam, int N, int K)
{
    int M;
    if constexpr (MSEL == 1)      M = 8 * g_ns;
    else if constexpr (MSEL == 2) M = 8 * g_nt;
    else                          M = Mparam;
    int rowBase = blockIdx.y * 128;
    if (rowBase >= M) return;

    const float* A;
    if constexpr (AS == 1)      A = g_m;
    else if constexpr (AS == 2) A = g_mc;
    else if constexpr (AS == 3) A = g_tgt;
    else                        A = Aext;
    const float* B;
    if constexpr (BS == 1)      B = g_wihT;
    else                        B = Bext;
    float* C;
    if constexpr (CS == 1)      C = g_h;
    else if constexpr (CS == 2) C = g_hc;
    else if constexpr (CS == 3) C = g_h2;
    else                        C = g_gi;

    const int BK = 16;
    __shared__ __align__(16) float As[2][BK][128];
    __shared__ __align__(16) float Bs[2][BK][128];
    int tid = threadIdx.x;
    int tx = tid % 16, ty = tid / 16;
    int colBase = blockIdx.x * 128;

    unsigned long long acc2[8][4];
#pragma unroll
    for (int i = 0; i < 8; i++)
#pragma unroll
        for (int j = 0; j < 4; j++) acc2[i][j] = 0ULL;

    int aRow = tid & 127;
    int aK   = (tid >> 7) * 8;
    int bRow = tid >> 4;
    int bC   = (tid & 15) * 4;

    int gr = rowBase + aRow;
    bool rowOK = (gr < M);
    const float* Arow = A + (size_t)(rowOK ? gr : 0) * K + aK;

    float4 va0, va1, vb0, vb1;

    va0 = make_float4(0.f, 0.f, 0.f, 0.f);
    va1 = make_float4(0.f, 0.f, 0.f, 0.f);
    if (rowOK) {
        va0 = *(const float4*)(Arow);
        va1 = *(const float4*)(Arow + 4);
    }
    vb0 = *(const float4*)(B + (size_t)bRow * N + colBase + bC);
    vb1 = *(const float4*)(B + (size_t)bRow * N + colBase + 64 + bC);
    As[0][aK + 0][aRow] = va0.x; As[0][aK + 1][aRow] = va0.y;
    As[0][aK + 2][aRow] = va0.z; As[0][aK + 3][aRow] = va0.w;
    As[0][aK + 4][aRow] = va1.x; As[0][aK + 5][aRow] = va1.y;
    As[0][aK + 6][aRow] = va1.z; As[0][aK + 7][aRow] = va1.w;
    *(float4*)&Bs[0][bRow][bC] = vb0;
    *(float4*)&Bs[0][bRow][64 + bC] = vb1;
    __syncthreads();

    int buf = 0;
    for (int k0 = 0; k0 < K; k0 += BK) {
        bool hasNext = (k0 + BK < K);
        if (hasNext) {
            int kn = k0 + BK;
            va0 = make_float4(0.f, 0.f, 0.f, 0.f);
            va1 = make_float4(0.f, 0.f, 0.f, 0.f);
            if (rowOK) {
                va0 = *(const float4*)(Arow + kn);
                va1 = *(const float4*)(Arow + kn + 4);
            }
            vb0 = *(const float4*)(B + (size_t)(kn + bRow) * N + colBase + bC);
            vb1 = *(const float4*)(B + (size_t)(kn + bRow) * N + colBase + 64 + bC);
        }
#pragma unroll
        for (int kk = 0; kk < BK; kk++) {
            float4 a0 = *(const float4*)&As[buf][kk][ty * 8];
            float4 a1 = *(const float4*)&As[buf][kk][ty * 8 + 4];
            unsigned long long av[8];
            av[0] = bcast2(a0.x); av[1] = bcast2(a0.y);
            av[2] = bcast2(a0.z); av[3] = bcast2(a0.w);
            av[4] = bcast2(a1.x); av[5] = bcast2(a1.y);
            av[6] = bcast2(a1.z); av[7] = bcast2(a1.w);
            ulonglong2 b0 = *(const ulonglong2*)&Bs[buf][kk][tx * 4];
            ulonglong2 b1 = *(const ulonglong2*)&Bs[buf][kk][64 + tx * 4];
            unsigned long long bv[4] = {b0.x, b0.y, b1.x, b1.y};
#pragma unroll
            for (int i = 0; i < 8; i++)
#pragma unroll
                for (int j = 0; j < 4; j++) ffma2(acc2[i][j], av[i], bv[j]);
        }
        if (hasNext) {
            int nb = buf ^ 1;
            As[nb][aK + 0][aRow] = va0.x; As[nb][aK + 1][aRow] = va0.y;
            As[nb][aK + 2][aRow] = va0.z; As[nb][aK + 3][aRow] = va0.w;
            As[nb][aK + 4][aRow] = va1.x; As[nb][aK + 5][aRow] = va1.y;
            As[nb][aK + 6][aRow] = va1.z; As[nb][aK + 7][aRow] = va1.w;
            *(float4*)&Bs[nb][bRow][bC] = vb0;
            *(float4*)&Bs[nb][bRow][64 + bC] = vb1;
            __syncthreads();
        }
        buf ^= 1;
    }

#pragma unroll
    for (int i = 0; i < 8; i++) {
        int grr = rowBase + ty * 8 + i;
        if (grr >= M) continue;
        float c[8];
#pragma unroll
        for (int j = 0; j < 4; j++) unpk2(c[2 * j], c[2 * j + 1], acc2[i][j]);
        int gc0 = colBase + tx * 4;
        int gc1 = colBase + 64 + tx * 4;
        float4 o0, o1;
        o0.x = c[0]; o0.y = c[1]; o0.z = c[2]; o0.w = c[3];
        o1.x = c[4]; o1.y = c[5]; o1.z = c[6]; o1.w = c[7];
        if (BIAS) {
            o0.x += bias[gc0]; o0.y += bias[gc0 + 1];
            o0.z += bias[gc0 + 2]; o0.w += bias[gc0 + 3];
            o1.x += bias[gc1]; o1.y += bias[gc1 + 1];
            o1.z += bias[gc1 + 2]; o1.w += bias[gc1 + 3];
        }
        if (RELU) {
            o0.x = fmaxf(o0.x, 0.f); o0.y = fmaxf(o0.y, 0.f);
            o0.z = fmaxf(o0.z, 0.f); o0.w = fmaxf(o0.w, 0.f);
            o1.x = fmaxf(o1.x, 0.f); o1.y = fmaxf(o1.y, 0.f);
            o1.z = fmaxf(o1.z, 0.f); o1.w = fmaxf(o1.w, 0.f);
        }
        *(float4*)(C + (size_t)grr * N + gc0) = o0;
        *(float4*)(C + (size_t)grr * N + gc1) = o1;
    }
}

// ------------------------- fused preprocessing -------------------------
__global__ void k_init() {
    int i = blockIdx.x * blockDim.x + threadIdx.x;
    if (i < NNODE) { g_deg[i] = 1; g_fill[i] = 1; g_tmask[i] = 0; g_smask[i] = 0; }
    if (i == 0) { g_nt = 0; g_ns = 0; }
}

__global__ void k_detect(const unsigned int* __restrict__ wdata, int n_elems) {
    __shared__ int bad;
    if (threadIdx.x == 0) bad = 0;
    __syncthreads();
    int limit = n_elems < 4096 ? n_elems : 4096;
    for (int i = threadIdx.x; i < limit; i += blockDim.x)
        if (wdata[2 * i + 1] != 0u) bad = 1;
    __syncthreads();
    if (threadIdx.x == 0) g_is64 = bad ? 0 : 1;
}

__device__ __forceinline__ int clampN(int v) {
    return v < 0 ? 0 : (v >= NNODE ? NNODE - 1 : v);
}

__global__ void k_cvt_ti_markt(const void* __restrict__ ti) {
    int b = blockIdx.x * blockDim.x + threadIdx.x;
    if (b < BB) {
        int v;
        if (g_is64) v = (int)((const long long*)ti)[b];
        else        v = ((const int*)ti)[b];
        int node = clampN(v);
        g_ti[b] = node;
        g_tmask[node] = 1;
        g_smask[node] = 1;
    }
}

__global__ void k_cvt_edges_deg(const void* __restrict__ ei) {
    int e = blockIdx.x * blockDim.x + threadIdx.x;
    if (e < NE) {
        int s, d;
        if (g_is64) {
            const long long* p = (const long long*)ei;
            s = (int)p[e]; d = (int)p[NE + e];
        } else {
            const int* p = (const int*)ei;
            s = p[e]; d = p[NE + e];
        }
        s = clampN(s); d = clampN(d);
        g_src[e] = s;
        g_dst[e] = d;
        atomicAdd(&g_deg[d], 1);
    }
}

__global__ void k_scan() {
    const int CH = 40;
    int t = threadIdx.x;
    int lane = t & 31, wid = t >> 5;
    int beg = t * CH;
    int sum = 0;
    for (int i = 0; i < CH; i++) {
        int idx = beg + i;
        if (idx < NNODE) sum += g_deg[idx];
    }
    int v = sum;
    for (int o = 1; o < 32; o <<= 1) {
        int u = __shfl_up_sync(0xffffffffu, v, o);
        if (lane >= o) v += u;
    }
    __shared__ int wsum[32];
    if (lane == 31) wsum[wid] = v;
    __syncthreads();
    if (wid == 0) {
        int w2 = wsum[lane];
        for (int o = 1; o < 32; o <<= 1) {
            int u = __shfl_up_sync(0xffffffffu, w2, o);
            if (lane >= o) w2 += u;
        }
        wsum[lane] = w2;
    }
    __syncthreads();
    int run = v - sum + (wid > 0 ? wsum[wid - 1] : 0);
    for (int i = 0; i < CH; i++) {
        int idx = beg + i;
        if (idx < NNODE) {
            int dg = g_deg[idx];
            g_rowptr[idx] = run;
            g_dinv[idx] = rsqrtf((float)dg);
            run += dg;
        }
    }
    if (t == 1023) g_rowptr[NNODE] = run;
}

// selfloop + fill fused (g_fill initialized to 1 -> slot 0 reserved for self loop)
__global__ void k_csr() {
    int i = blockIdx.x * blockDim.x + threadIdx.x;
    if (i < NNODE) {
        int pos = g_rowptr[i];
        g_col[pos] = i;
        float d = g_dinv[i];
        g_val[pos] = d * d;
    } else if (i < NNODE + NE) {
        int e = i - NNODE;
        int s = g_src[e];
        int d = g_dst[e];
        int pos = g_rowptr[d] + atomicAdd(&g_fill[d], 1);
        g_col[pos] = s;
        g_val[pos] = g_dinv[s] * g_dinv[d];
    }
}

__global__ void k_mark_s() {
    int e = blockIdx.x * blockDim.x + threadIdx.x;
    if (e < NE && g_tmask[g_dst[e]]) g_smask[g_src[e]] = 1;
}
__global__ void k_compact() {
    int n = blockIdx.x * blockDim.x + threadIdx.x;
    if (n < NNODE) {
        if (g_tmask[n]) {
            int ix = atomicAdd(&g_nt, 1);
            g_tnodes[ix] = n;
            g_tidx[n] = ix;
        }
        if (g_smask[n]) {
            int ix = atomicAdd(&g_ns, 1);
            g_snodes[ix] = n;
            g_sidx[n] = ix;
        }
    }
}

// ------------------------- batched aggregations (4-way unrolled MLP) -----------------
__device__ __forceinline__ void fma4(float4& a, float v, float4 x) {
    a.x = fmaf(v, x.x, a.x); a.y = fmaf(v, x.y, a.y);
    a.z = fmaf(v, x.z, a.z); a.w = fmaf(v, x.w, a.w);
}

__global__ void k_agg1_all()
{
    int warp = (blockIdx.x * blockDim.x + threadIdx.x) >> 5;
    int lane = threadIdx.x & 31;
    int ns = g_ns;
    if (warp >= TT * ns) return;
    int t = warp / ns;
    int i = warp - t * ns;
    int node = g_snodes[i];
    int s0 = g_rowptr[node], s1 = g_rowptr[node + 1];
    const float4* h4 = (const float4*)g_h;
    size_t hbase = (size_t)t * NNODE * 32;
    float4 a0 = make_float4(0.f, 0.f, 0.f, 0.f);
    float4 a1 = a0, a2 = a0, a3 = a0;
    int e = s0;
    for (; e + 4 <= s1; e += 4) {
        int c0 = g_col[e], c1 = g_col[e + 1], c2 = g_col[e + 2], c3 = g_col[e + 3];
        float v0 = g_val[e], v1 = g_val[e + 1], v2 = g_val[e + 2], v3 = g_val[e + 3];
        float4 x0 = h4[hbase + (size_t)c0 * 32 + lane];
        float4 x1 = h4[hbase + (size_t)c1 * 32 + lane];
        float4 x2 = h4[hbase + (size_t)c2 * 32 + lane];
        float4 x3 = h4[hbase + (size_t)c3 * 32 + lane];
        fma4(a0, v0, x0); fma4(a1, v1, x1); fma4(a2, v2, x2); fma4(a3, v3, x3);
    }
    for (; e < s1; e++)
        fma4(a0, g_val[e], h4[hbase + (size_t)g_col[e] * 32 + lane]);
    a0.x += a1.x + a2.x + a3.x; a0.y += a1.y + a2.y + a3.y;
    a0.z += a1.z + a2.z + a3.z; a0.w += a1.w + a2.w + a3.w;
    ((float4*)g_m)[(size_t)warp * 32 + lane] = a0;
}

__global__ void k_agg2_all()
{
    int warp = (blockIdx.x * blockDim.x + threadIdx.x) >> 5;
    int lane = threadIdx.x & 31;
    int nt = g_nt;
    if (warp >= TT * nt) return;
    int t = warp / nt;
    int i = warp - t * nt;
    int node = g_tnodes[i];
    int s0 = g_rowptr[node], s1 = g_rowptr[node + 1];
    const float4* h4 = (const float4*)g_hc;
    size_t hbase = (size_t)t * g_ns * 32;
    float4 a0 = make_float4(0.f, 0.f, 0.f, 0.f);
    float4 a1 = a0, a2 = a0, a3 = a0;
    int e = s0;
    for (; e + 4 <= s1; e += 4) {
        int c0 = g_sidx[g_col[e]],     c1 = g_sidx[g_col[e + 1]];
        int c2 = g_sidx[g_col[e + 2]], c3 = g_sidx[g_col[e + 3]];
        float v0 = g_val[e], v1 = g_val[e + 1], v2 = g_val[e + 2], v3 = g_val[e + 3];
        float4 x0 = h4[hbase + (size_t)c0 * 32 + lane];
        float4 x1 = h4[hbase + (size_t)c1 * 32 + lane];
        float4 x2 = h4[hbase + (size_t)c2 * 32 + lane];
        float4 x3 = h4[hbase + (size_t)c3 * 32 + lane];
        fma4(a0, v0, x0); fma4(a1, v1, x1); fma4(a2, v2, x2); fma4(a3, v3, x3);
    }
    for (; e < s1; e++)
        fma4(a0, g_val[e], h4[hbase + (size_t)g_sidx[g_col[e]] * 32 + lane]);
    a0.x += a1.x + a2.x + a3.x; a0.y += a1.y + a2.y + a3.y;
    a0.z += a1.z + a2.z + a3.z; a0.w += a1.w + a2.w + a3.w;
    ((float4*)g_mc)[(size_t)warp * 32 + lane] = a0;      // FIX: was g_h2 in R16
}

// ------------------------- gather targets (all t) -------------------------
__global__ void k_gather_all() {
    int b = blockIdx.x;
    int t = blockIdx.y;
    int f = threadIdx.x;                   // 256
    int node = g_ti[b];
    float v = (f < GG) ? g_hc[((size_t)t * g_ns + g_sidx[node]) * GG + f]
                       : g_h2[((size_t)t * g_nt + g_tidx[node]) * GG + (f - GG)];
    g_tgt[((size_t)t * BB + b) * (2 * GG) + f] = v;
}

// ------------------------- weight transpose for GI GEMM -------------------------
__global__ void k_transpose_wih(const float* __restrict__ w) {
    int i = blockIdx.x * blockDim.x + threadIdx.x;
    if (i < 384 * 256) {
        int jj = i / 256, k = i % 256;
        g_wihT[(size_t)k * 384 + jj] = w[i];
    }
}

// ------------------------- fused persistent GRU (R15 winner) -------------------------
__device__ __forceinline__ float sigmoidf_(float x) { return 1.f / (1.f + expf(-x)); }

__global__ void __launch_bounds__(384) k_gru_fused(const float* __restrict__ whh,
                                                   const float* __restrict__ b_hh)
{
    __shared__ float sh_h[8][128];
    __shared__ float sh_g[8][384];
    int j = threadIdx.x;
    int rowBase = blockIdx.x * 8;

    for (int idx = j; idx < 8 * 128; idx += 384) ((float*)sh_h)[idx] = 0.f;
    __syncthreads();

    const float* wrow = whh + (size_t)j * 128;
    float bj = b_hh[j];

    for (int t = 0; t < TT; t++) {
        float acc[8];
#pragma unroll
        for (int r = 0; r < 8; r++) acc[r] = bj;
#pragma unroll 4
        for (int k = 0; k < 128; k += 4) {
            float4 w4 = *(const float4*)(wrow + k);
#pragma unroll
            for (int r = 0; r < 8; r++) {
                float4 h4 = *(const float4*)&sh_h[r][k];
                acc[r] = fmaf(h4.x, w4.x, acc[r]);
                acc[r] = fmaf(h4.y, w4.y, acc[r]);
                acc[r] = fmaf(h4.z, w4.z, acc[r]);
                acc[r] = fmaf(h4.w, w4.w, acc[r]);
            }
        }
#pragma unroll
        for (int r = 0; r < 8; r++) sh_g[r][j] = acc[r];
        __syncthreads();
        for (int idx = j; idx < 8 * 128; idx += 384) {
            int r = idx >> 7, c = idx & 127;
            int b = rowBase + r;
            size_t gir = ((size_t)t * BB + b) * 384;
            float hr = sh_g[r][c], hz = sh_g[r][128 + c], hg = sh_g[r][256 + c];
            float rr = sigmoidf_(g_gi[gir + c] + hr);
            float zz = sigmoidf_(g_gi[gir + 128 + c] + hz);
            float gg = tanhf(g_gi[gir + 256 + c] + rr * hg);
            float hn = (1.f - zz) * gg + zz * sh_h[r][c];
            sh_h[r][c] = hn;
            g_outs[((size_t)t * BB + b) * HH + c] = hn;
        }
        __syncthreads();
    }
}

// ------------------------- attention + prediction head -------------------------
__global__ void k_final(const float* __restrict__ attn_w, const float* __restrict__ attn_b,
                        const float* __restrict__ pw1, const float* __restrict__ pb1,
                        const float* __restrict__ pw2, const float* __restrict__ pb2,
                        float* __restrict__ out)
{
    int b = blockIdx.x;
    int j = threadIdx.x;                   // 128
    __shared__ float so[TT][HH];
    __shared__ float red[HH];
    __shared__ float sc[TT];
    __shared__ float w8[TT];
    __shared__ float hm[16];

#pragma unroll
    for (int t = 0; t < TT; t++) so[t][j] = g_outs[((size_t)t * BB + b) * HH + j];
    float aw = attn_w[j];
    __syncthreads();

    for (int t = 0; t < TT; t++) {
        red[j] = so[t][j] * aw;
        __syncthreads();
        for (int off = 64; off > 0; off >>= 1) {
            if (j < off) red[j] += red[j + off];
            __syncthreads();
        }
        if (j == 0) sc[t] = tanhf(red[0] + attn_b[0]);
        __syncthreads();
    }
    if (j == 0) {
        float mx = sc[0];
        for (int t = 1; t < TT; t++) mx = fmaxf(mx, sc[t]);
        float s = 0.f;
        for (int t = 0; t < TT; t++) { w8[t] = expf(sc[t] - mx); s += w8[t]; }
        float inv = 1.f / s;
        for (int t = 0; t < TT; t++) w8[t] *= inv;
    }
    __syncthreads();
    float rep = 0.f;
#pragma unroll
    for (int t = 0; t < TT; t++) rep = fmaf(w8[t], so[t][j], rep);
    red[j] = rep;
    __syncthreads();
    if (j < 16) {
        float s = pb1[j];
        for (int k = 0; k < HH; k++) s = fmaf(red[k], pw1[k * 16 + j], s);
        hm[j] = fmaxf(s, 0.f);
    }
    __syncthreads();
    if (j == 0) {
        float p = pb2[0];
#pragma unroll
        for (int k = 0; k < 16; k++) p = fmaf(hm[k], pw2[k], p);
        out[b] = p;
    }
    if (j < TT) out[BB + b * TT + j] = w8[j];
}

// ------------------------- launch -------------------------
extern "C" void kernel_launch(void* const* d_in, const int* in_sizes, int n_in,
                              void* d_out, int out_size)
{
    const float* x       = (const float*)d_in[0];
    const void*  ei      = d_in[1];
    const void*  ti      = d_in[2];
    const float* proj_w  = (const float*)d_in[3];
    const float* proj_b  = (const float*)d_in[4];
    const float* gcn_w1  = (const float*)d_in[5];
    const float* gcn_b1  = (const float*)d_in[6];
    const float* gcn_w2  = (const float*)d_in[7];
    const float* gcn_b2  = (const float*)d_in[8];
    const float* gru_w_ih = (const float*)d_in[9];
    const float* gru_w_hh = (const float*)d_in[10];
    const float* gru_b_ih = (const float*)d_in[11];
    const float* gru_b_hh = (const float*)d_in[12];
    const float* attn_w  = (const float*)d_in[13];
    const float* attn_b  = (const float*)d_in[14];
    const float* pred_w1 = (const float*)d_in[15];
    const float* pred_b1 = (const float*)d_in[16];
    const float* pred_w2 = (const float*)d_in[17];
    const float* pred_b2 = (const float*)d_in[18];
    float* out = (float*)d_out;

    dim3 gAll(1, (MALL + 127) / 128);
    dim3 gG2(1, (TT * BB + 127) / 128);
    dim3 gGi(3, (TT * BB + 127) / 128);
    const int agg1Blocks = (MALL * 32 + 255) / 256;
    const int agg2Blocks = (TT * BB * 32 + 255) / 256;
    dim3 gGather(BB, TT);

    // index 3 = batched proj GEMM (ncu captures launch 3)
    k_init<<<(NNODE + 255) / 256, 256>>>();                                      // 0
    k_detect<<<1, 1024>>>((const unsigned int*)ei, BB);                          // 1
    k_cvt_ti_markt<<<(BB + 255) / 256, 256>>>(ti);                               // 2
    sgemm2<0, 0, 1, 0, true, true><<<gAll, 256>>>(x, proj_w, proj_b, MALL, PP, FF); // 3
    k_cvt_edges_deg<<<(NE + 255) / 256, 256>>>(ei);                              // 4
    k_transpose_wih<<<(384 * 256 + 255) / 256, 256>>>(gru_w_ih);                 // 5

    k_scan<<<1, 1024>>>();
    k_csr<<<(NNODE + NE + 255) / 256, 256>>>();
    k_mark_s<<<(NE + 255) / 256, 256>>>();
    k_compact<<<(NNODE + 255) / 256, 256>>>();

    // GCN via linearity: agg first, GEMM on compact rows
    k_agg1_all<<<agg1Blocks, 256>>>();
    sgemm2<1, 0, 2, 1, true, true><<<gAll, 256>>>(nullptr, gcn_w1, gcn_b1, 0, GG, PP);
    k_agg2_all<<<agg2Blocks, 256>>>();
    sgemm2<2, 0, 3, 2, true, true><<<gG2, 256>>>(nullptr, gcn_w2, gcn_b2, 0, GG, GG);
    k_gather_all<<<gGather, 256>>>();

    // GI = tgt (8192 x 256) @ wihT + b_ih
    sgemm2<3, 1, 4, 0, false, true><<<gGi, 256>>>(nullptr, nullptr, gru_b_ih, TT * BB, 3 * HH, 2 * GG);

    // fused GRU: all 8 steps in one persistent kernel
    k_gru_fused<<<BB / 8, 384>>>(gru_w_hh, gru_b_hh);

    k_final<<<BB, HH>>>(attn_w, attn_b, pred_w1, pred_b1, pred_w2, pred_b2, out);
}